// round 5
// baseline (speedup 1.0000x reference)
#include <cuda_runtime.h>
#include <cuda_bf16.h>
#include <cstdint>

#define N_NODES 100000
#define N_EDGES 1600000
#define DIM     128

// ---------------- scratch (static device globals; no allocs) ----------------
__device__ float g_h[(size_t)N_NODES * DIM];   // projected features, 51.2 MB
__device__ int   g_count[N_NODES];
__device__ int   g_cursor[N_NODES];
__device__ int   g_start[N_NODES + 1];
__device__ int   g_colp[N_EDGES];
__device__ float g_valp[N_EDGES];

// ---------------- 1) GEMM: h = x @ W  (fp32, packed f32x2 FMA) --------------
// W (128x128 fp32 = 64 KB) in dynamic smem. 256 threads = 8 warps.
// Each warp handles a PAIR of rows: lanes 0-15 -> row0, lanes 16-31 -> row1.
// Each lane owns 8 output columns as 4 packed f32x2 accumulators.
__global__ void __launch_bounds__(256) gemm_kernel(const float* __restrict__ x,
                                                   const float* __restrict__ W) {
    extern __shared__ float sW[];  // [128][128]
    const int tid = threadIdx.x;
    for (int i = tid * 4; i < DIM * DIM; i += blockDim.x * 4) {
        *(float4*)&sW[i] = *(const float4*)&W[i];
    }
    __syncthreads();

    const int lane    = tid & 31;
    const int warp    = tid >> 5;
    const int half    = lane >> 4;           // sub-row within the pair
    const int colbase = (lane & 15) * 8;     // 16 lanes * 8 cols = 128 cols
    const int npairs  = N_NODES / 2;         // 50000

    for (int pair = blockIdx.x * 8 + warp; pair < npairs; pair += gridDim.x * 8) {
        const int row = pair * 2 + half;
        const float* __restrict__ xr = x + (size_t)row * DIM;

        unsigned long long acc0 = 0ull, acc1 = 0ull, acc2 = 0ull, acc3 = 0ull;

        #pragma unroll 4
        for (int k = 0; k < DIM; ++k) {
            const float xv = __ldg(&xr[k]);
            unsigned long long xx;
            asm("mov.b64 %0, {%1, %1};" : "=l"(xx) : "f"(xv));
            const unsigned long long* wrow =
                (const unsigned long long*)&sW[k * DIM + colbase];
            const unsigned long long w0 = wrow[0];
            const unsigned long long w1 = wrow[1];
            const unsigned long long w2 = wrow[2];
            const unsigned long long w3 = wrow[3];
            asm("fma.rn.f32x2 %0, %1, %2, %0;" : "+l"(acc0) : "l"(xx), "l"(w0));
            asm("fma.rn.f32x2 %0, %1, %2, %0;" : "+l"(acc1) : "l"(xx), "l"(w1));
            asm("fma.rn.f32x2 %0, %1, %2, %0;" : "+l"(acc2) : "l"(xx), "l"(w2));
            asm("fma.rn.f32x2 %0, %1, %2, %0;" : "+l"(acc3) : "l"(xx), "l"(w3));
        }

        float a0, a1, a2, a3, a4, a5, a6, a7;
        asm("mov.b64 {%0, %1}, %2;" : "=f"(a0), "=f"(a1) : "l"(acc0));
        asm("mov.b64 {%0, %1}, %2;" : "=f"(a2), "=f"(a3) : "l"(acc1));
        asm("mov.b64 {%0, %1}, %2;" : "=f"(a4), "=f"(a5) : "l"(acc2));
        asm("mov.b64 {%0, %1}, %2;" : "=f"(a6), "=f"(a7) : "l"(acc3));

        float* __restrict__ hp = g_h + (size_t)row * DIM + colbase;
        *(float4*)&hp[0] = make_float4(a0, a1, a2, a3);
        *(float4*)&hp[4] = make_float4(a4, a5, a6, a7);
    }
}

// ---------------- 2) CSR build: zero -> histogram -> scan -> scatter --------
__global__ void zero_kernel() {
    int i = blockIdx.x * blockDim.x + threadIdx.x;
    if (i < N_NODES) {
        g_count[i]  = 0;
        g_cursor[i] = 0;
    }
}

__global__ void hist_kernel(const int* __restrict__ rows) {
    int i = blockIdx.x * blockDim.x + threadIdx.x;
    if (i < N_EDGES) atomicAdd(&g_count[rows[i]], 1);
}

// Single-block exclusive scan of g_count -> g_start (100001 entries).
__global__ void __launch_bounds__(1024) scan_kernel() {
    __shared__ int ssum[1024];
    const int t  = threadIdx.x;
    const int CH = (N_NODES + 1023) / 1024;  // 98
    const int lo = t * CH;
    const int hi = (lo + CH < N_NODES) ? (lo + CH) : N_NODES;

    int s = 0;
    for (int i = lo; i < hi; ++i) s += g_count[i];
    ssum[t] = s;
    __syncthreads();

    // Hillis-Steele inclusive scan over thread sums
    for (int off = 1; off < 1024; off <<= 1) {
        const int v   = ssum[t];
        const int add = (t >= off) ? ssum[t - off] : 0;
        __syncthreads();
        ssum[t] = v + add;
        __syncthreads();
    }

    int base = (t == 0) ? 0 : ssum[t - 1];   // exclusive prefix for my chunk
    for (int i = lo; i < hi; ++i) {
        g_start[i] = base;
        base += g_count[i];
    }
    if (t == 1023) g_start[N_NODES] = ssum[1023];
}

__global__ void scatter_kernel(const int* __restrict__ rows,
                               const int* __restrict__ cols,
                               const float* __restrict__ vals) {
    int i = blockIdx.x * blockDim.x + threadIdx.x;
    if (i < N_EDGES) {
        const int r   = rows[i];
        const int pos = g_start[r] + atomicAdd(&g_cursor[r], 1);
        g_colp[pos] = cols[i];
        g_valp[pos] = vals[i];
    }
}

// ---------------- 3) SpMM: warp per row, lane owns 4 dims -------------------
__global__ void __launch_bounds__(256) spmm_kernel(float* __restrict__ out) {
    const int gwarp = (blockIdx.x * blockDim.x + threadIdx.x) >> 5;
    const int lane  = threadIdx.x & 31;
    if (gwarp >= N_NODES) return;

    const int s = g_start[gwarp];
    const int e = g_start[gwarp + 1];

    float4 acc = make_float4(0.f, 0.f, 0.f, 0.f);

    // software-pipelined col/val prefetch (breaks col->gather dependent chain)
    int   col = 0;
    float v   = 0.f;
    if (s < e) { col = g_colp[s]; v = g_valp[s]; }

    for (int j = s; j < e; ++j) {
        const int   ccol = col;
        const float cv   = v;
        if (j + 1 < e) { col = g_colp[j + 1]; v = g_valp[j + 1]; }
        const float4 hv = *(const float4*)&g_h[(size_t)ccol * DIM + (lane << 2)];
        acc.x += cv * hv.x;
        acc.y += cv * hv.y;
        acc.z += cv * hv.z;
        acc.w += cv * hv.w;
    }

    *(float4*)&out[(size_t)gwarp * DIM + (lane << 2)] = acc;
}

// ---------------- launch ------------------------------------------------------
extern "C" void kernel_launch(void* const* d_in, const int* in_sizes, int n_in,
                              void* d_out, int out_size) {
    const float* x    = (const float*)d_in[0];
    const float* W    = (const float*)d_in[1];
    const float* vals = (const float*)d_in[2];
    const int*   rows = (const int*)d_in[3];
    const int*   cols = (const int*)d_in[4];
    float*       out  = (float*)d_out;

    // 64 KB dynamic smem for the W tile (idempotent; not a stream op)
    cudaFuncSetAttribute(gemm_kernel,
                         cudaFuncAttributeMaxDynamicSharedMemorySize, 65536);

    // 1) dense projection
    gemm_kernel<<<444, 256, 65536>>>(x, W);

    // 2) CSR build
    zero_kernel<<<(N_NODES + 255) / 256, 256>>>();
    hist_kernel<<<(N_EDGES + 255) / 256, 256>>>(rows);
    scan_kernel<<<1, 1024>>>();
    scatter_kernel<<<(N_EDGES + 255) / 256, 256>>>(rows, cols, vals);

    // 3) gather + segment-reduce, one warp per output row
    const int spmm_threads = N_NODES * 32;
    spmm_kernel<<<(spmm_threads + 255) / 256, 256>>>(out);
}

// round 6
// speedup vs baseline: 3.2231x; 3.2231x over previous
#include <cuda_runtime.h>
#include <cuda_bf16.h>
#include <cstdint>

#define N_NODES 100000
#define N_EDGES 1600000
#define DIM     128

#define TILE_ROWS   64
#define NTILES      ((N_NODES + TILE_ROWS - 1) / TILE_ROWS)   // 1563
#define SCAN_BLKSZ  1024
#define SCAN_NBLK   ((N_NODES + SCAN_BLKSZ - 1) / SCAN_BLKSZ) // 98

// ---------------- scratch (static device globals; no allocs) ----------------
__device__ float g_h[(size_t)N_NODES * DIM];   // projected features, 51.2 MB
__device__ int   g_count[N_NODES];
__device__ int   g_cursor[N_NODES];
__device__ int   g_start[N_NODES + 1];
__device__ int2  g_cv[N_EDGES];                // packed (col, val-bits)
__device__ int   g_bsum[SCAN_NBLK];
__device__ int   g_boff[SCAN_NBLK];

// ---------------- helpers ----------------------------------------------------
__device__ __forceinline__ unsigned long long dup2(float v) {
    unsigned long long r;
    asm("mov.b64 %0, {%1, %1};" : "=l"(r) : "f"(v));
    return r;
}
__device__ __forceinline__ void fma2(unsigned long long& a,
                                     unsigned long long x,
                                     unsigned long long w) {
    asm("fma.rn.f32x2 %0, %1, %2, %0;" : "+l"(a) : "l"(x), "l"(w));
}

// ---------------- 1) GEMM: h = x @ W  ----------------------------------------
// Persistent blocks. W (64 KB) loaded to smem once per block; per tile a
// 64x128 x slab (32 KB) is staged. Each thread owns an 8-row x 4-col output
// tile: 16 f32x2 accumulators, W pairs read directly as ulonglong2 from smem.
__global__ void __launch_bounds__(256, 2)
gemm_kernel(const float* __restrict__ x, const float* __restrict__ W) {
    extern __shared__ float smem[];
    float* sW = smem;                 // [128][128]
    float* sX = smem + DIM * DIM;     // [64][128]

    const int tid = threadIdx.x;
    // load W once
    for (int i = tid * 4; i < DIM * DIM; i += 256 * 4)
        *(float4*)&sW[i] = *(const float4*)&W[i];

    const int colg = tid & 31;        // 32 col-groups * 4 cols = 128 cols
    const int rowg = tid >> 5;        // 8 row-groups * 8 rows = 64 rows

    for (int tile = blockIdx.x; tile < NTILES; tile += gridDim.x) {
        const int base = tile * TILE_ROWS;
        __syncthreads();  // previous tile's sX reads done (also covers sW 1st iter)
        // stage x tile: 64*128 floats = 2048 float4, 8 per thread
        for (int i = tid; i < TILE_ROWS * DIM / 4; i += 256) {
            const int r = i >> 5;                 // float4-row (32 float4/row)
            const int c = (i & 31) * 4;
            float4 v = make_float4(0.f, 0.f, 0.f, 0.f);
            if (base + r < N_NODES)
                v = *(const float4*)&x[(size_t)(base + r) * DIM + c];
            *(float4*)&sX[r * DIM + c] = v;
        }
        __syncthreads();

        unsigned long long acc[8][2];
        #pragma unroll
        for (int r = 0; r < 8; ++r) { acc[r][0] = 0ull; acc[r][1] = 0ull; }

        #pragma unroll 2
        for (int k4 = 0; k4 < DIM; k4 += 4) {
            ulonglong2 w0 = *(const ulonglong2*)&sW[(k4 + 0) * DIM + colg * 4];
            ulonglong2 w1 = *(const ulonglong2*)&sW[(k4 + 1) * DIM + colg * 4];
            ulonglong2 w2 = *(const ulonglong2*)&sW[(k4 + 2) * DIM + colg * 4];
            ulonglong2 w3 = *(const ulonglong2*)&sW[(k4 + 3) * DIM + colg * 4];
            #pragma unroll
            for (int r = 0; r < 8; ++r) {
                const float4 xv = *(const float4*)&sX[(rowg * 8 + r) * DIM + k4];
                unsigned long long xd;
                xd = dup2(xv.x); fma2(acc[r][0], xd, w0.x); fma2(acc[r][1], xd, w0.y);
                xd = dup2(xv.y); fma2(acc[r][0], xd, w1.x); fma2(acc[r][1], xd, w1.y);
                xd = dup2(xv.z); fma2(acc[r][0], xd, w2.x); fma2(acc[r][1], xd, w2.y);
                xd = dup2(xv.w); fma2(acc[r][0], xd, w3.x); fma2(acc[r][1], xd, w3.y);
            }
        }

        #pragma unroll
        for (int r = 0; r < 8; ++r) {
            const int row = base + rowg * 8 + r;
            if (row < N_NODES) {
                const float2 a = *(const float2*)&acc[r][0];
                const float2 b = *(const float2*)&acc[r][1];
                *(float4*)&g_h[(size_t)row * DIM + colg * 4] =
                    make_float4(a.x, a.y, b.x, b.y);
            }
        }
    }
}

// ---------------- 2) CSR build ------------------------------------------------
__global__ void zero_kernel() {
    int i = blockIdx.x * blockDim.x + threadIdx.x;
    if (i < N_NODES) { g_count[i] = 0; g_cursor[i] = 0; }
}

__global__ void hist_kernel(const int* __restrict__ rows) {
    int i = blockIdx.x * blockDim.x + threadIdx.x;
    if (i < N_EDGES) atomicAdd(&g_count[rows[i]], 1);
}

// scan stage 1: per-block sums (98 blocks x 1024 elements)
__global__ void __launch_bounds__(256) scan_reduce_kernel() {
    __shared__ int ssum[8];
    const int tid  = threadIdx.x;
    const int lane = tid & 31;
    const int warp = tid >> 5;
    const int idx  = blockIdx.x * SCAN_BLKSZ + tid * 4;

    int s = 0;
    if (idx + 3 < N_NODES) {
        int4 c = *(const int4*)&g_count[idx];
        s = c.x + c.y + c.z + c.w;
    } else {
        for (int j = 0; j < 4; ++j) if (idx + j < N_NODES) s += g_count[idx + j];
    }
    for (int o = 16; o > 0; o >>= 1) s += __shfl_down_sync(~0u, s, o);
    if (lane == 0) ssum[warp] = s;
    __syncthreads();
    if (tid == 0) {
        int t = 0;
        #pragma unroll
        for (int w = 0; w < 8; ++w) t += ssum[w];
        g_bsum[blockIdx.x] = t;
    }
}

// scan stage 2: 1 block scans the 98 block sums -> exclusive offsets + total
__global__ void __launch_bounds__(128) scan_mid_kernel() {
    __shared__ int sv[128];
    const int t = threadIdx.x;
    int v = (t < SCAN_NBLK) ? g_bsum[t] : 0;
    sv[t] = v;
    __syncthreads();
    for (int o = 1; o < 128; o <<= 1) {
        const int cur = sv[t];
        const int add = (t >= o) ? sv[t - o] : 0;
        __syncthreads();
        sv[t] = cur + add;
        __syncthreads();
    }
    if (t < SCAN_NBLK) g_boff[t] = sv[t] - v;          // exclusive
    if (t == SCAN_NBLK - 1) g_start[N_NODES] = sv[t];  // total = N_EDGES
}

// scan stage 3: per-block exclusive scan + block offset -> g_start
__global__ void __launch_bounds__(256) scan_final_kernel() {
    __shared__ int swsum[8];
    const int tid  = threadIdx.x;
    const int lane = tid & 31;
    const int warp = tid >> 5;
    const int idx  = blockIdx.x * SCAN_BLKSZ + tid * 4;

    int c0 = 0, c1 = 0, c2 = 0, c3 = 0;
    if (idx + 3 < N_NODES) {
        int4 c = *(const int4*)&g_count[idx];
        c0 = c.x; c1 = c.y; c2 = c.z; c3 = c.w;
    } else {
        if (idx + 0 < N_NODES) c0 = g_count[idx + 0];
        if (idx + 1 < N_NODES) c1 = g_count[idx + 1];
        if (idx + 2 < N_NODES) c2 = g_count[idx + 2];
        if (idx + 3 < N_NODES) c3 = g_count[idx + 3];
    }
    const int ts = c0 + c1 + c2 + c3;

    int incl = ts;
    for (int o = 1; o < 32; o <<= 1) {
        const int n = __shfl_up_sync(~0u, incl, o);
        if (lane >= o) incl += n;
    }
    if (lane == 31) swsum[warp] = incl;
    __syncthreads();
    if (tid == 0) {
        int run = 0;
        #pragma unroll
        for (int w = 0; w < 8; ++w) { const int t2 = swsum[w]; swsum[w] = run; run += t2; }
    }
    __syncthreads();

    int e = g_boff[blockIdx.x] + swsum[warp] + (incl - ts);  // exclusive base
    if (idx + 0 < N_NODES) g_start[idx + 0] = e; e += c0;
    if (idx + 1 < N_NODES) g_start[idx + 1] = e; e += c1;
    if (idx + 2 < N_NODES) g_start[idx + 2] = e; e += c2;
    if (idx + 3 < N_NODES) g_start[idx + 3] = e;
}

__global__ void scatter_kernel(const int* __restrict__ rows,
                               const int* __restrict__ cols,
                               const float* __restrict__ vals) {
    int i = blockIdx.x * blockDim.x + threadIdx.x;
    if (i < N_EDGES) {
        const int r   = rows[i];
        const int pos = g_start[r] + atomicAdd(&g_cursor[r], 1);
        g_cv[pos] = make_int2(cols[i], __float_as_int(vals[i]));
    }
}

// ---------------- 3) SpMM: warp per row, lane owns 4 dims --------------------
__global__ void __launch_bounds__(256) spmm_kernel(float* __restrict__ out) {
    const int gwarp = (blockIdx.x * blockDim.x + threadIdx.x) >> 5;
    const int lane  = threadIdx.x & 31;
    if (gwarp >= N_NODES) return;

    const int s = g_start[gwarp];
    const int e = g_start[gwarp + 1];

    float4 acc = make_float4(0.f, 0.f, 0.f, 0.f);

    int2 cv = make_int2(0, 0);
    if (s < e) cv = g_cv[s];

    for (int j = s; j < e; ++j) {
        const int   ccol = cv.x;
        const float v    = __int_as_float(cv.y);
        if (j + 1 < e) cv = g_cv[j + 1];
        const float4 hv = *(const float4*)&g_h[(size_t)ccol * DIM + (lane << 2)];
        acc.x += v * hv.x;
        acc.y += v * hv.y;
        acc.z += v * hv.z;
        acc.w += v * hv.w;
    }

    *(float4*)&out[(size_t)gwarp * DIM + (lane << 2)] = acc;
}

// ---------------- launch ------------------------------------------------------
extern "C" void kernel_launch(void* const* d_in, const int* in_sizes, int n_in,
                              void* d_out, int out_size) {
    const float* x    = (const float*)d_in[0];
    const float* W    = (const float*)d_in[1];
    const float* vals = (const float*)d_in[2];
    const int*   rows = (const int*)d_in[3];
    const int*   cols = (const int*)d_in[4];
    float*       out  = (float*)d_out;

    const int smem_bytes = (DIM * DIM + TILE_ROWS * DIM) * (int)sizeof(float); // 96 KB
    cudaFuncSetAttribute(gemm_kernel,
                         cudaFuncAttributeMaxDynamicSharedMemorySize, smem_bytes);

    // 1) dense projection (persistent, 2 blocks/SM)
    gemm_kernel<<<296, 256, smem_bytes>>>(x, W);

    // 2) CSR build
    zero_kernel<<<(N_NODES + 255) / 256, 256>>>();
    hist_kernel<<<(N_EDGES + 255) / 256, 256>>>(rows);
    scan_reduce_kernel<<<SCAN_NBLK, 256>>>();
    scan_mid_kernel<<<1, 128>>>();
    scan_final_kernel<<<SCAN_NBLK, 256>>>();
    scatter_kernel<<<(N_EDGES + 255) / 256, 256>>>(rows, cols, vals);

    // 3) gather + segment-reduce, one warp per output row
    spmm_kernel<<<(N_NODES * 32 + 255) / 256, 256>>>(out);
}